// round 16
// baseline (speedup 1.0000x reference)
#include <cuda_runtime.h>
#include <stdint.h>

// Problem constants
#define TT 2048
#define BB 128
#define KK 64
#define NTHREADS 1024  // 32 warps: 0-1 = A/C + 1 row each; 2-31 = B rows

// ---------------------------------------------------------------------------
// mbarrier helpers (shared-memory, cta scope)
// ---------------------------------------------------------------------------
__device__ __forceinline__ void mbar_init(uint32_t addr, uint32_t count) {
    asm volatile("mbarrier.init.shared.b64 [%0], %1;"
                 :: "r"(addr), "r"(count) : "memory");
}
__device__ __forceinline__ void mbar_arrive(uint32_t addr) {
    asm volatile("mbarrier.arrive.release.cta.shared::cta.b64 _, [%0];"
                 :: "r"(addr) : "memory");
}
__device__ __forceinline__ void mbar_wait(uint32_t addr, uint32_t parity) {
    asm volatile(
        "{\n\t"
        ".reg .pred P;\n"
        "WL_%=:\n\t"
        "mbarrier.try_wait.parity.acquire.cta.shared::cta.b64 P, [%0], %1, 0x989680;\n\t"
        "@P bra.uni WD_%=;\n\t"
        "bra.uni WL_%=;\n"
        "WD_%=:\n\t"
        "}"
        :: "r"(addr), "r"(parity) : "memory");
}

// ---------------------------------------------------------------------------
// Threefry-2x32, 20 rounds, exactly as jax._src.prng.threefry2x32 (SHF rotate)
// ---------------------------------------------------------------------------
__device__ __forceinline__ uint2 tf2x32(uint32_t k0, uint32_t k1,
                                        uint32_t x0, uint32_t x1) {
    uint32_t ks2 = k0 ^ k1 ^ 0x1BD11BDAu;
    x0 += k0; x1 += k1;
#define TFR(r) { x0 += x1; x1 = __funnelshift_l(x1, x1, (r)); x1 ^= x0; }
    TFR(13) TFR(15) TFR(26) TFR(6)
    x0 += k1; x1 += ks2 + 1u;
    TFR(17) TFR(29) TFR(16) TFR(24)
    x0 += ks2; x1 += k0 + 2u;
    TFR(13) TFR(15) TFR(26) TFR(6)
    x0 += k0; x1 += k1 + 3u;
    TFR(17) TFR(29) TFR(16) TFR(24)
    x0 += k1; x1 += ks2 + 4u;
    TFR(13) TFR(15) TFR(26) TFR(6)
    x0 += ks2; x1 += k0 + 5u;
#undef TFR
    return make_uint2(x0, x1);
}

__device__ __forceinline__ float bits_to_u01(uint32_t bits) {
    return __uint_as_float((bits >> 9) | 0x3f800000u) - 1.0f;
}

#define TINYF 1.17549435082228751e-38f

// FAST: e2 = -log2(u) via MUFU.LG2. Error <= ~4e-7; the hybrid abs+rel margin
// routes every possibly-affected row to the exact reference path.
__device__ __forceinline__ float neglog2_mufu(uint32_t bits) {
    float u = fmaxf(bits_to_u01(bits), TINYF);
    float l;
    asm("lg2.approx.f32 %0, %1;" : "=f"(l) : "f"(u));
    return -l;
}

// XLA/CHLO ErfInv32 polynomial (Giles) -- precise path (feeds state)
__device__ __forceinline__ float erfinv_xla(float x) {
    float w = -log1pf(-x * x);
    float p;
    if (w < 5.0f) {
        w = w - 2.5f;
        p = 2.81022636e-08f;
        p = fmaf(p, w, 3.43273939e-07f);
        p = fmaf(p, w, -3.5233877e-06f);
        p = fmaf(p, w, -4.39150654e-06f);
        p = fmaf(p, w, 0.00021858087f);
        p = fmaf(p, w, -0.00125372503f);
        p = fmaf(p, w, -0.00417768164f);
        p = fmaf(p, w, 0.246640727f);
        p = fmaf(p, w, 1.50140941f);
    } else {
        w = sqrtf(w) - 3.0f;
        p = -0.000200214257f;
        p = fmaf(p, w, 0.000100950558f);
        p = fmaf(p, w, 0.00134934322f);
        p = fmaf(p, w, -0.00367342844f);
        p = fmaf(p, w, 0.00573950773f);
        p = fmaf(p, w, -0.0076224613f);
        p = fmaf(p, w, 0.00943887047f);
        p = fmaf(p, w, 1.00167406f);
        p = fmaf(p, w, 2.83297682f);
    }
    return p * x;
}

// Exact reference gumbel (libdevice logf), used only on fallback rows.
__device__ __forceinline__ float gumbel_exact(uint32_t bits) {
    float u = bits_to_u01(bits);
    float v = fmaxf(u, TINYF);
    return -logf(-logf(v));
}

// ---------------------------------------------------------------------------
// Fill the 4 constant columns of pf_out once
// ---------------------------------------------------------------------------
__global__ void fill_const_kernel(const float* __restrict__ params,
                                  float* __restrict__ pf) {
    const float p0 = params[0], p1 = params[1], p2 = params[2], p3 = params[3];
    const size_t n = (size_t)TT * KK * BB;
    size_t idx = (size_t)blockIdx.x * blockDim.x + threadIdx.x;
    if (idx < n) {
        float* o = pf + idx * 5;
        o[0] = p0; o[1] = p1; o[2] = p2; o[3] = p3;
    }
}

// B2 body for one row: REDUX argmin with hybrid-margin exact fallback.
__device__ __forceinline__ int b2_row(float e0, float e1,
                                      uint32_t bb0, uint32_t bb1,
                                      float ra, float rb,
                                      const float* q_s, int lane) {
    const float MARGIN_REL = 1.0003f;
    const float MARGIN_ABS = 3e-4f;
    float t0 = e0 * ra;            // positive -> uint-monotone
    float t1 = e1 * rb;
    uint32_t k0 = (__float_as_uint(t0) & 0xFFFFFFC0u) | (uint32_t)lane;
    uint32_t k1 = (__float_as_uint(t1) & 0xFFFFFFC0u) | (uint32_t)(lane + 32);
    uint32_t km = k0 < k1 ? k0 : k1;
    uint32_t wk = __reduce_min_sync(0xffffffffu, km);
    int bj = (int)(wk & 63u);
    float bw = __uint_as_float(wk & 0xFFFFFFC0u);
    float thr = fmaf(bw, MARGIN_REL, MARGIN_ABS);
    bool nr = ((lane      != bj) && (t0 <= thr)) ||
              ((lane + 32 != bj) && (t1 <= thr));
    if (__ballot_sync(0xffffffffu, nr)) {
        float s0 = gumbel_exact(bb0) + logf(q_s[lane]);
        float s1 = gumbel_exact(bb1) + logf(q_s[lane + 32]);
        float fb; int fj;
        if (s1 > s0) { fb = s1; fj = lane + 32; }
        else         { fb = s0; fj = lane; }
#pragma unroll
        for (int o = 16; o; o >>= 1) {
            float ov = __shfl_xor_sync(0xffffffffu, fb, o);
            int   oj = __shfl_xor_sync(0xffffffffu, fj, o);
            if (ov > fb || (ov == fb && oj < fj)) { fb = ov; fj = oj; }
        }
        bj = fj;
    }
    return bj;
}

// ---------------------------------------------------------------------------
// Persistent kernel: 1 CTA per batch element b. 32 warps:
//   warps 0-1 : phase A + own categorical row (62/63) + C (w0)
//   warps 2-3 : 3 rows each (0..5); warps 4-31: 2 rows each (6..61)
// mbarriers: RINV (64 arrivals, A lanes) / IDX (1024 arrivals, all lanes).
// ---------------------------------------------------------------------------
__global__ void __launch_bounds__(NTHREADS, 1)
garch_pf_kernel(const float* __restrict__ obs,     // (B, T, 2)
                const float* __restrict__ vol0,    // (K*B, 1)
                const float* __restrict__ params,  // (4,)
                float* __restrict__ out) {
    const int b    = blockIdx.x;
    const int tid  = threadIdx.x;
    const int lane = tid & 31;
    const int warp = tid >> 5;

    __shared__ uint2 skey[TT];     // per-step key_t
    __shared__ uint2 sckey[TT];    // fold_in(key_t, 1)
    __shared__ float r_s[TT];      // obs[b, t, 0]
    __shared__ float rinv_s[KK];   // ln2 / q   (fast-key scale)
    __shared__ float q_s[KK];      // q (fallback + phase C)
    __shared__ float nv_s[KK], wn_s[KK];
    __shared__ float vol_s[KK], w_s[KK];
    __shared__ int   idx_s[KK];
    __shared__ float redm_s[2], reds_s[2];
    __shared__ alignas(8) uint64_t mb_rinv, mb_idx;

    const uint32_t a_rinv = (uint32_t)__cvta_generic_to_shared(&mb_rinv);
    const uint32_t a_idx  = (uint32_t)__cvta_generic_to_shared(&mb_idx);

    if (tid == 0) {
        mbar_init(a_rinv, 64);      // A-warp lanes
        mbar_init(a_idx, 1024);     // all lanes (B2 completion, all warps)
    }
    for (int t = tid; t < TT; t += NTHREADS) {
        uint2 kt = tf2x32(0u, 42u, 0u, (uint32_t)t);
        skey[t]  = kt;
        sckey[t] = tf2x32(kt.x, kt.y, 0u, 1u);
        r_s[t]   = obs[((size_t)b * TT + t) * 2];
    }
    if (warp < 2) {
        const int pa = warp * 32 + lane;
        vol_s[pa] = vol0[pa * BB + b];
        w_s[pa]   = 1.0f / 64.0f;
    }
    const float c0 = params[0], q1 = params[1], q2 = params[2], r1 = params[3];
    const float r1e = 0.001f * r1;
    __syncthreads();

    float* __restrict__ y_out = out;                    // (T, B, 1)
    float* __restrict__ pf    = out + (size_t)TT * BB;  // (T, K*B, 5)

    const float MINVAL_N = -0.99999994039535522f;
    const float SQRT2    = 1.41421356237309515f;
    const float LOG2PI   = 1.83787706640934534f;
    const float ALPHA_F  = 0.3f;
    const float UNIFW    = (float)((1.0 - 0.3) / 64.0);
    const float LN2F     = 0.69314718055994531f;
    const uint32_t bb64  = (uint32_t)(b * KK);

    if (warp < 2) {
        // ================= A/C warps (+ 1 categorical row each) =============
        const int pa   = warp * 32 + lane;
        const int myrow = 62 + warp;
        float svra = 0.f, svrb = 0.f, spy = 0.f;   // step t-1 outputs (w0)
        float    e0, e1;
        uint32_t bb0, bb1;

        // B1(0) for own row
        {
            const uint2 ck = sckey[0];
            const uint32_t cb = (uint32_t)myrow * 8192u + bb64;
            uint2 ga = tf2x32(ck.x, ck.y, 0u, cb + (uint32_t)lane);
            uint2 gb = tf2x32(ck.x, ck.y, 0u, cb + (uint32_t)lane + 32u);
            bb0 = ga.x ^ ga.y; bb1 = gb.x ^ gb.y;
            e0 = neglog2_mufu(bb0); e1 = neglog2_mufu(bb1);
        }

        for (int t = 0; t < TT; t++) {
            // ---- Phase A(t) -------------------------------------------------
            {
                const uint2 kt = skey[t];
                const float r    = r_s[t];
                const float rr   = r * r;
                const float q2rr = (q2 * r) * r;

                uint2 bl = tf2x32(kt.x, kt.y, 0u, (uint32_t)(pa * BB + b));
                float u  = bits_to_u01(bl.x ^ bl.y);
                float v  = fmaxf(MINVAL_N, u * 2.0f + MINVAL_N);
                float eps = SQRT2 * erfinv_xla(v);
                float x   = ((c0 + q1 * vol_s[pa]) + q2rr) + r1e * eps;
                float nvv = fabsf(x) + 1e-8f;
                float ll  = -0.5f * ((rr / nvv + logf(nvv)) + LOG2PI);
                float lw  = logf(w_s[pa] + 1e-12f) + ll;

                float m = lw;
#pragma unroll
                for (int o = 16; o; o >>= 1)
                    m = fmaxf(m, __shfl_xor_sync(0xffffffffu, m, o));
                if (lane == 0) redm_s[warp] = m;
                asm volatile("bar.sync 1, 64;" ::: "memory");
                float mm = fmaxf(redm_s[0], redm_s[1]);
                float s  = expf(lw - mm);
#pragma unroll
                for (int o = 16; o; o >>= 1)
                    s += __shfl_xor_sync(0xffffffffu, s, o);
                if (lane == 0) reds_s[warp] = s;
                asm volatile("bar.sync 1, 64;" ::: "memory");
                float lse = logf(reds_s[0] + reds_s[1]) + mm;

                float wn = expf(lw - lse);
                float q  = ALPHA_F * wn + UNIFW;
                nv_s[pa]   = nvv;
                wn_s[pa]   = wn;
                q_s[pa]    = q;
                rinv_s[pa] = LN2F / q;
            }
            mbar_arrive(a_rinv);        // per-lane release -> 64 arrivals
            // cross-A-warp visibility of rinv/q for our own B2
            asm volatile("bar.sync 1, 64;" ::: "memory");

            // ---- B2(t) for own row ------------------------------------------
            {
                int bj = b2_row(e0, e1, bb0, bb1,
                                rinv_s[lane], rinv_s[lane + 32], q_s, lane);
                if (lane == 0) idx_s[myrow] = bj;
            }
            mbar_arrive(a_idx);

            // ---- stores of step t-1 (w0 slack) -------------------------------
            if (warp == 0 && t > 0) {
                float y = spy;
#pragma unroll
                for (int o = 16; o; o >>= 1)
                    y += __shfl_xor_sync(0xffffffffu, y, o);
                if (lane == 0) y_out[(size_t)(t - 1) * BB + b] = y;
                pf[((size_t)(t - 1) * (KK * BB) + (size_t)lane * BB + b) * 5 + 4] = svra;
                pf[((size_t)(t - 1) * (KK * BB) + (size_t)(lane + 32) * BB + b) * 5 + 4] = svrb;
            }

            // ---- B1(t+1) for own row (fills former idle window) --------------
            if (t + 1 < TT) {
                const uint2 ck = sckey[t + 1];
                const uint32_t cb = (uint32_t)myrow * 8192u + bb64;
                uint2 ga = tf2x32(ck.x, ck.y, 0u, cb + (uint32_t)lane);
                uint2 gb = tf2x32(ck.x, ck.y, 0u, cb + (uint32_t)lane + 32u);
                bb0 = ga.x ^ ga.y; bb1 = gb.x ^ gb.y;
                e0 = neglog2_mufu(bb0); e1 = neglog2_mufu(bb1);
            }

            if (warp == 0) {
                // ---- wait for idx(t) (all B2 reads done), then C(t) ----------
                mbar_wait(a_idx, (uint32_t)(t & 1));
                const int ia = idx_s[lane], ib = idx_s[lane + 32];
                float vra = nv_s[ia], vrb = nv_s[ib];
                float wra = wn_s[ia] / q_s[ia];
                float wrb = wn_s[ib] / q_s[ib];
                float ssum = wra + wrb;
#pragma unroll
                for (int o = 16; o; o >>= 1)
                    ssum += __shfl_xor_sync(0xffffffffu, ssum, o);
                wra /= ssum; wrb /= ssum;
                vol_s[lane]      = vra; vol_s[lane + 32] = vrb;
                w_s[lane]        = wra; w_s[lane + 32]   = wrb;
                svra = vra; svrb = vrb;
                spy  = vra * wra + vrb * wrb;
            }
            // bar1: w1 may not start A(t+1) until w0 finished C(t)
            asm volatile("bar.sync 1, 64;" ::: "memory");
        }
        // final step's outputs
        if (warp == 0) {
            float y = spy;
#pragma unroll
            for (int o = 16; o; o >>= 1)
                y += __shfl_xor_sync(0xffffffffu, y, o);
            if (lane == 0) y_out[(size_t)(TT - 1) * BB + b] = y;
            pf[((size_t)(TT - 1) * (KK * BB) + (size_t)lane * BB + b) * 5 + 4] = svra;
            pf[((size_t)(TT - 1) * (KK * BB) + (size_t)(lane + 32) * BB + b) * 5 + 4] = svrb;
        }
    } else {
        // ================= B warps (categorical rows) =======================
        // w2 = warp-2 in 0..29: w2<2 -> 3 rows at w2*3 (rows 0..5);
        // else 2 rows at 6+(w2-2)*2 (rows 6..61).
        const int w2    = warp - 2;
        const int nrows = (w2 < 2) ? 3 : 2;
        const int row0  = (w2 < 2) ? w2 * 3 : 6 + (w2 - 2) * 2;

        float    e0v[3], e1v[3];
        uint32_t b0v[3], b1v[3];

        for (int t = 0; t < TT; t++) {
            // ---- B1(t): state-independent, at this warp's own pace ----------
            {
                const uint2 ck = sckey[t];
#pragma unroll
                for (int ii = 0; ii < 3; ii++) {
                    if (ii < nrows) {
                        const uint32_t cb = (uint32_t)(row0 + ii) * 8192u + bb64;
                        uint2 ga = tf2x32(ck.x, ck.y, 0u, cb + (uint32_t)lane);
                        uint2 gb = tf2x32(ck.x, ck.y, 0u, cb + (uint32_t)lane + 32u);
                        b0v[ii] = ga.x ^ ga.y;
                        b1v[ii] = gb.x ^ gb.y;
                        e0v[ii] = neglog2_mufu(b0v[ii]);
                        e1v[ii] = neglog2_mufu(b1v[ii]);
                    }
                }
            }
            // ---- wait only on A ---------------------------------------------
            mbar_wait(a_rinv, (uint32_t)(t & 1));
            {
                const float ra = rinv_s[lane];
                const float rb = rinv_s[lane + 32];
#pragma unroll
                for (int ii = 0; ii < 3; ii++) {
                    if (ii < nrows) {
                        int bj = b2_row(e0v[ii], e1v[ii], b0v[ii], b1v[ii],
                                        ra, rb, q_s, lane);
                        if (lane == 0) idx_s[row0 + ii] = bj;
                    }
                }
            }
            mbar_arrive(a_idx);   // per-lane release; flow into B1(t+1)
        }
    }
}

// ---------------------------------------------------------------------------
extern "C" void kernel_launch(void* const* d_in, const int* in_sizes, int n_in,
                              void* d_out, int out_size) {
    const float* obs    = (const float*)d_in[0];  // (128, 2048, 2)
    const float* vol0   = (const float*)d_in[1];  // (8192, 1)
    const float* params = (const float*)d_in[2];  // (4,)
    float* out = (float*)d_out;

    float* pf = out + (size_t)TT * BB;
    fill_const_kernel<<<65536, 256>>>(params, pf);
    garch_pf_kernel<<<BB, NTHREADS>>>(obs, vol0, params, out);
}

// round 17
// speedup vs baseline: 1.0467x; 1.0467x over previous
#include <cuda_runtime.h>
#include <stdint.h>

// Problem constants
#define TT 2048
#define BB 128
#define KK 64
#define NTHREADS 1024  // 32 warps: 0-1 = A/C ONLY; 2-31 = B rows (4x3 + 26x2)

// ---------------------------------------------------------------------------
// mbarrier helpers (shared-memory, cta scope)
// ---------------------------------------------------------------------------
__device__ __forceinline__ void mbar_init(uint32_t addr, uint32_t count) {
    asm volatile("mbarrier.init.shared.b64 [%0], %1;"
                 :: "r"(addr), "r"(count) : "memory");
}
__device__ __forceinline__ void mbar_arrive(uint32_t addr) {
    asm volatile("mbarrier.arrive.release.cta.shared::cta.b64 _, [%0];"
                 :: "r"(addr) : "memory");
}
__device__ __forceinline__ void mbar_wait(uint32_t addr, uint32_t parity) {
    asm volatile(
        "{\n\t"
        ".reg .pred P;\n"
        "WL_%=:\n\t"
        "mbarrier.try_wait.parity.acquire.cta.shared::cta.b64 P, [%0], %1, 0x989680;\n\t"
        "@P bra.uni WD_%=;\n\t"
        "bra.uni WL_%=;\n"
        "WD_%=:\n\t"
        "}"
        :: "r"(addr), "r"(parity) : "memory");
}

// ---------------------------------------------------------------------------
// Threefry-2x32, 20 rounds, exactly as jax._src.prng.threefry2x32 (SHF rotate)
// ---------------------------------------------------------------------------
__device__ __forceinline__ uint2 tf2x32(uint32_t k0, uint32_t k1,
                                        uint32_t x0, uint32_t x1) {
    uint32_t ks2 = k0 ^ k1 ^ 0x1BD11BDAu;
    x0 += k0; x1 += k1;
#define TFR(r) { x0 += x1; x1 = __funnelshift_l(x1, x1, (r)); x1 ^= x0; }
    TFR(13) TFR(15) TFR(26) TFR(6)
    x0 += k1; x1 += ks2 + 1u;
    TFR(17) TFR(29) TFR(16) TFR(24)
    x0 += ks2; x1 += k0 + 2u;
    TFR(13) TFR(15) TFR(26) TFR(6)
    x0 += k0; x1 += k1 + 3u;
    TFR(17) TFR(29) TFR(16) TFR(24)
    x0 += k1; x1 += ks2 + 4u;
    TFR(13) TFR(15) TFR(26) TFR(6)
    x0 += ks2; x1 += k0 + 5u;
#undef TFR
    return make_uint2(x0, x1);
}

__device__ __forceinline__ float bits_to_u01(uint32_t bits) {
    return __uint_as_float((bits >> 9) | 0x3f800000u) - 1.0f;
}

#define TINYF 1.17549435082228751e-38f

// FAST: e2 = -log2(u) via MUFU.LG2. Error <= ~4e-7; the hybrid abs+rel margin
// routes every possibly-affected row to the exact reference path.
__device__ __forceinline__ float neglog2_mufu(uint32_t bits) {
    float u = fmaxf(bits_to_u01(bits), TINYF);
    float l;
    asm("lg2.approx.f32 %0, %1;" : "=f"(l) : "f"(u));
    return -l;
}

// XLA/CHLO ErfInv32 polynomial (Giles) -- precise path (feeds state)
__device__ __forceinline__ float erfinv_xla(float x) {
    float w = -log1pf(-x * x);
    float p;
    if (w < 5.0f) {
        w = w - 2.5f;
        p = 2.81022636e-08f;
        p = fmaf(p, w, 3.43273939e-07f);
        p = fmaf(p, w, -3.5233877e-06f);
        p = fmaf(p, w, -4.39150654e-06f);
        p = fmaf(p, w, 0.00021858087f);
        p = fmaf(p, w, -0.00125372503f);
        p = fmaf(p, w, -0.00417768164f);
        p = fmaf(p, w, 0.246640727f);
        p = fmaf(p, w, 1.50140941f);
    } else {
        w = sqrtf(w) - 3.0f;
        p = -0.000200214257f;
        p = fmaf(p, w, 0.000100950558f);
        p = fmaf(p, w, 0.00134934322f);
        p = fmaf(p, w, -0.00367342844f);
        p = fmaf(p, w, 0.00573950773f);
        p = fmaf(p, w, -0.0076224613f);
        p = fmaf(p, w, 0.00943887047f);
        p = fmaf(p, w, 1.00167406f);
        p = fmaf(p, w, 2.83297682f);
    }
    return p * x;
}

// Exact reference gumbel (libdevice logf), used only on fallback rows.
__device__ __forceinline__ float gumbel_exact(uint32_t bits) {
    float u = bits_to_u01(bits);
    float v = fmaxf(u, TINYF);
    return -logf(-logf(v));
}

// ---------------------------------------------------------------------------
// Fill the 4 constant columns of pf_out once
// ---------------------------------------------------------------------------
__global__ void fill_const_kernel(const float* __restrict__ params,
                                  float* __restrict__ pf) {
    const float p0 = params[0], p1 = params[1], p2 = params[2], p3 = params[3];
    const size_t n = (size_t)TT * KK * BB;
    size_t idx = (size_t)blockIdx.x * blockDim.x + threadIdx.x;
    if (idx < n) {
        float* o = pf + idx * 5;
        o[0] = p0; o[1] = p1; o[2] = p2; o[3] = p3;
    }
}

// B2 body for one row: REDUX argmin with hybrid-margin exact fallback.
__device__ __forceinline__ int b2_row(float e0, float e1,
                                      uint32_t bb0, uint32_t bb1,
                                      float ra, float rb,
                                      const float* q_s, int lane) {
    const float MARGIN_REL = 1.0003f;
    const float MARGIN_ABS = 3e-4f;
    float t0 = e0 * ra;            // positive -> uint-monotone
    float t1 = e1 * rb;
    uint32_t k0 = (__float_as_uint(t0) & 0xFFFFFFC0u) | (uint32_t)lane;
    uint32_t k1 = (__float_as_uint(t1) & 0xFFFFFFC0u) | (uint32_t)(lane + 32);
    uint32_t km = k0 < k1 ? k0 : k1;
    uint32_t wk = __reduce_min_sync(0xffffffffu, km);
    int bj = (int)(wk & 63u);
    float bw = __uint_as_float(wk & 0xFFFFFFC0u);
    float thr = fmaf(bw, MARGIN_REL, MARGIN_ABS);
    bool nr = ((lane      != bj) && (t0 <= thr)) ||
              ((lane + 32 != bj) && (t1 <= thr));
    if (__ballot_sync(0xffffffffu, nr)) {
        float s0 = gumbel_exact(bb0) + logf(q_s[lane]);
        float s1 = gumbel_exact(bb1) + logf(q_s[lane + 32]);
        float fb; int fj;
        if (s1 > s0) { fb = s1; fj = lane + 32; }
        else         { fb = s0; fj = lane; }
#pragma unroll
        for (int o = 16; o; o >>= 1) {
            float ov = __shfl_xor_sync(0xffffffffu, fb, o);
            int   oj = __shfl_xor_sync(0xffffffffu, fj, o);
            if (ov > fb || (ov == fb && oj < fj)) { fb = ov; fj = oj; }
        }
        bj = fj;
    }
    return bj;
}

// ---------------------------------------------------------------------------
// Persistent kernel: 1 CTA per batch element b. 32 warps:
//   warps 0-1 : phase A + C ONLY (r15-verbatim; the serial recurrence path)
//   warps 2-5 : 3 rows each (0..11); warps 6-31: 2 rows each (12..63)
// mbarriers: RINV (64 arrivals, A lanes) / IDX (960 arrivals, B lanes).
// ---------------------------------------------------------------------------
__global__ void __launch_bounds__(NTHREADS, 1)
garch_pf_kernel(const float* __restrict__ obs,     // (B, T, 2)
                const float* __restrict__ vol0,    // (K*B, 1)
                const float* __restrict__ params,  // (4,)
                float* __restrict__ out) {
    const int b    = blockIdx.x;
    const int tid  = threadIdx.x;
    const int lane = tid & 31;
    const int warp = tid >> 5;

    __shared__ uint2 skey[TT];     // per-step key_t
    __shared__ uint2 sckey[TT];    // fold_in(key_t, 1)
    __shared__ float r_s[TT];      // obs[b, t, 0]
    __shared__ float rinv_s[KK];   // ln2 / q   (fast-key scale)
    __shared__ float q_s[KK];      // q (fallback + phase C)
    __shared__ float nv_s[KK], wn_s[KK];
    __shared__ float vol_s[KK], w_s[KK];
    __shared__ int   idx_s[KK];
    __shared__ float redm_s[2], reds_s[2];
    __shared__ alignas(8) uint64_t mb_rinv, mb_idx;

    const uint32_t a_rinv = (uint32_t)__cvta_generic_to_shared(&mb_rinv);
    const uint32_t a_idx  = (uint32_t)__cvta_generic_to_shared(&mb_idx);

    if (tid == 0) {
        mbar_init(a_rinv, 64);      // A-warp lanes
        mbar_init(a_idx, 960);      // 30 B-warps x 32 lanes
    }
    for (int t = tid; t < TT; t += NTHREADS) {
        uint2 kt = tf2x32(0u, 42u, 0u, (uint32_t)t);
        skey[t]  = kt;
        sckey[t] = tf2x32(kt.x, kt.y, 0u, 1u);
        r_s[t]   = obs[((size_t)b * TT + t) * 2];
    }
    if (warp < 2) {
        const int pa = warp * 32 + lane;
        vol_s[pa] = vol0[pa * BB + b];
        w_s[pa]   = 1.0f / 64.0f;
    }
    const float c0 = params[0], q1 = params[1], q2 = params[2], r1 = params[3];
    const float r1e = 0.001f * r1;
    __syncthreads();

    float* __restrict__ y_out = out;                    // (T, B, 1)
    float* __restrict__ pf    = out + (size_t)TT * BB;  // (T, K*B, 5)

    const float MINVAL_N = -0.99999994039535522f;
    const float SQRT2    = 1.41421356237309515f;
    const float LOG2PI   = 1.83787706640934534f;
    const float ALPHA_F  = 0.3f;
    const float UNIFW    = (float)((1.0 - 0.3) / 64.0);
    const float LN2F     = 0.69314718055994531f;
    const uint32_t bb64  = (uint32_t)(b * KK);

    if (warp < 2) {
        // ================= A/C warps (pure; r15-verbatim) ===================
        const int pa = warp * 32 + lane;
        float svra = 0.f, svrb = 0.f, spy = 0.f;   // step t-1 outputs (w0)

        for (int t = 0; t < TT; t++) {
            // ---- Phase A(t): produce rinv/q/nv/wn ---------------------------
            {
                const uint2 kt = skey[t];
                const float r    = r_s[t];
                const float rr   = r * r;
                const float q2rr = (q2 * r) * r;

                uint2 bl = tf2x32(kt.x, kt.y, 0u, (uint32_t)(pa * BB + b));
                float u  = bits_to_u01(bl.x ^ bl.y);
                float v  = fmaxf(MINVAL_N, u * 2.0f + MINVAL_N);
                float eps = SQRT2 * erfinv_xla(v);
                float x   = ((c0 + q1 * vol_s[pa]) + q2rr) + r1e * eps;
                float nvv = fabsf(x) + 1e-8f;
                float ll  = -0.5f * ((rr / nvv + logf(nvv)) + LOG2PI);
                float lw  = logf(w_s[pa] + 1e-12f) + ll;

                // logsumexp over 64 across the two warps
                float m = lw;
#pragma unroll
                for (int o = 16; o; o >>= 1)
                    m = fmaxf(m, __shfl_xor_sync(0xffffffffu, m, o));
                if (lane == 0) redm_s[warp] = m;
                asm volatile("bar.sync 1, 64;" ::: "memory");
                float mm = fmaxf(redm_s[0], redm_s[1]);
                float s  = expf(lw - mm);
#pragma unroll
                for (int o = 16; o; o >>= 1)
                    s += __shfl_xor_sync(0xffffffffu, s, o);
                if (lane == 0) reds_s[warp] = s;
                asm volatile("bar.sync 1, 64;" ::: "memory");
                float lse = logf(reds_s[0] + reds_s[1]) + mm;

                float wn = expf(lw - lse);
                float q  = ALPHA_F * wn + UNIFW;
                nv_s[pa]   = nvv;
                wn_s[pa]   = wn;
                q_s[pa]    = q;
                rinv_s[pa] = LN2F / q;     // fold ln2 into the key scale
            }
            mbar_arrive(a_rinv);        // per-lane release -> 64 arrivals

            if (warp == 0) {
                // ---- stores of step t-1 (off the recurrence critical path) --
                if (t > 0) {
                    float y = spy;
#pragma unroll
                    for (int o = 16; o; o >>= 1)
                        y += __shfl_xor_sync(0xffffffffu, y, o);
                    if (lane == 0) y_out[(size_t)(t - 1) * BB + b] = y;
                    pf[((size_t)(t - 1) * (KK * BB) + (size_t)lane * BB + b) * 5 + 4] = svra;
                    pf[((size_t)(t - 1) * (KK * BB) + (size_t)(lane + 32) * BB + b) * 5 + 4] = svrb;
                }
                // ---- wait for idx(t) (all B2(t) reads done), then C(t) ------
                mbar_wait(a_idx, (uint32_t)(t & 1));
                const int ia = idx_s[lane], ib = idx_s[lane + 32];
                float vra = nv_s[ia], vrb = nv_s[ib];
                float wra = wn_s[ia] / q_s[ia];
                float wrb = wn_s[ib] / q_s[ib];
                float ssum = wra + wrb;
#pragma unroll
                for (int o = 16; o; o >>= 1)
                    ssum += __shfl_xor_sync(0xffffffffu, ssum, o);
                wra /= ssum; wrb /= ssum;
                vol_s[lane]      = vra; vol_s[lane + 32] = vrb;
                w_s[lane]        = wra; w_s[lane + 32]   = wrb;
                svra = vra; svrb = vrb;
                spy  = vra * wra + vrb * wrb;
            }
            // bar1: w1 may not start A(t+1) until w0 finished C(t)
            asm volatile("bar.sync 1, 64;" ::: "memory");
        }
        // final step's outputs
        if (warp == 0) {
            float y = spy;
#pragma unroll
            for (int o = 16; o; o >>= 1)
                y += __shfl_xor_sync(0xffffffffu, y, o);
            if (lane == 0) y_out[(size_t)(TT - 1) * BB + b] = y;
            pf[((size_t)(TT - 1) * (KK * BB) + (size_t)lane * BB + b) * 5 + 4] = svra;
            pf[((size_t)(TT - 1) * (KK * BB) + (size_t)(lane + 32) * BB + b) * 5 + 4] = svrb;
        }
    } else {
        // ================= B warps (categorical rows) =======================
        // w2 = warp-2 in 0..29: w2<4 -> 3 rows at w2*3 (rows 0..11);
        // else 2 rows at 12+(w2-4)*2 (rows 12..63).
        const int w2    = warp - 2;
        const int nrows = (w2 < 4) ? 3 : 2;
        const int row0  = (w2 < 4) ? w2 * 3 : 12 + (w2 - 4) * 2;

        float    e0v[3], e1v[3];
        uint32_t b0v[3], b1v[3];

        for (int t = 0; t < TT; t++) {
            // ---- B1(t): state-independent, at this warp's own pace ----------
            {
                const uint2 ck = sckey[t];
#pragma unroll
                for (int ii = 0; ii < 3; ii++) {
                    if (ii < nrows) {
                        const uint32_t cb = (uint32_t)(row0 + ii) * 8192u + bb64;
                        uint2 ga = tf2x32(ck.x, ck.y, 0u, cb + (uint32_t)lane);
                        uint2 gb = tf2x32(ck.x, ck.y, 0u, cb + (uint32_t)lane + 32u);
                        b0v[ii] = ga.x ^ ga.y;
                        b1v[ii] = gb.x ^ gb.y;
                        e0v[ii] = neglog2_mufu(b0v[ii]);
                        e1v[ii] = neglog2_mufu(b1v[ii]);
                    }
                }
            }
            // ---- wait only on A (never on sibling B-warps) ------------------
            mbar_wait(a_rinv, (uint32_t)(t & 1));
            {
                const float ra = rinv_s[lane];
                const float rb = rinv_s[lane + 32];
#pragma unroll
                for (int ii = 0; ii < 3; ii++) {
                    if (ii < nrows) {
                        int bj = b2_row(e0v[ii], e1v[ii], b0v[ii], b1v[ii],
                                        ra, rb, q_s, lane);
                        if (lane == 0) idx_s[row0 + ii] = bj;
                    }
                }
            }
            mbar_arrive(a_idx);   // per-lane release; flow into B1(t+1)
        }
    }
}

// ---------------------------------------------------------------------------
extern "C" void kernel_launch(void* const* d_in, const int* in_sizes, int n_in,
                              void* d_out, int out_size) {
    const float* obs    = (const float*)d_in[0];  // (128, 2048, 2)
    const float* vol0   = (const float*)d_in[1];  // (8192, 1)
    const float* params = (const float*)d_in[2];  // (4,)
    float* out = (float*)d_out;

    float* pf = out + (size_t)TT * BB;
    fill_const_kernel<<<65536, 256>>>(params, pf);
    garch_pf_kernel<<<BB, NTHREADS>>>(obs, vol0, params, out);
}